// round 15
// baseline (speedup 1.0000x reference)
#include <cuda_runtime.h>
#include <cuda_fp16.h>
#include <cstdint>

#define DIN   25
#define DP    128
#define NT    256        // 8 warps; warp w owns rows 32w..32w+31 of a 256-row tile
#define TROWS 256        // rows per CTA tile
#define W_LD  136        // halves per weight row (272B, conflict-free under ldmatrix)
#define XN_LD 40         // halves per xn row (80B)
#define WBYTES 3200      // per-warp x slice: 32 rows x 25 f32

// shared byte offsets (16B aligned)
#define SO_W1  0         // 32x136 half   = 8704
#define SO_W2  8704      // 128x136 half  = 34816
#define SO_XN  43520     // 256x40 half   = 20480
#define SO_XS  64000     // 256x25 f32    = 25600
#define SO_B1  89600     // 512
#define SO_B2  90112     // 512
#define SO_G   90624     // 128
#define SO_BT  90752     // 128
#define SMEM_BYTES 90880 // x2 CTAs fits 228KB/SM

__device__ __forceinline__ uint32_t s2u(const void* p) {
    uint32_t a;
    asm("{ .reg .u64 t; cvta.to.shared.u64 t, %1; cvt.u32.u64 %0, t; }" : "=r"(a) : "l"(p));
    return a;
}
__device__ __forceinline__ void ldsm4(uint32_t* r, uint32_t addr) {
    asm volatile("ldmatrix.sync.aligned.m8n8.x4.shared.b16 {%0,%1,%2,%3}, [%4];"
                 : "=r"(r[0]), "=r"(r[1]), "=r"(r[2]), "=r"(r[3]) : "r"(addr));
}
__device__ __forceinline__ void ldsm4t(uint32_t* r, uint32_t addr) {
    asm volatile("ldmatrix.sync.aligned.m8n8.x4.trans.shared.b16 {%0,%1,%2,%3}, [%4];"
                 : "=r"(r[0]), "=r"(r[1]), "=r"(r[2]), "=r"(r[3]) : "r"(addr));
}
__device__ __forceinline__ void mma16816(float* c, const uint32_t* a, uint32_t b0, uint32_t b1) {
    asm volatile("mma.sync.aligned.m16n8k16.row.col.f32.f16.f16.f32 "
                 "{%0,%1,%2,%3}, {%4,%5,%6,%7}, {%8,%9}, {%0,%1,%2,%3};"
                 : "+f"(c[0]), "+f"(c[1]), "+f"(c[2]), "+f"(c[3])
                 : "r"(a[0]), "r"(a[1]), "r"(a[2]), "r"(a[3]), "r"(b0), "r"(b1));
}
__device__ __forceinline__ uint32_t packh2(float lo, float hi) {
    __half2 h = __floats2half2_rn(lo, hi);
    return *(uint32_t*)&h;
}
// tanh-form GELU via hardware tanh (MUFU.TANH): branch-free.
__device__ __forceinline__ float gelu(float v) {
    float u = 0.7978845608028654f * fmaf(0.044715f * v, v * v, v);
    float t;
    asm("tanh.approx.f32 %0, %1;" : "=f"(t) : "f"(u));
    return 0.5f * v * (1.0f + t);
}
__device__ __forceinline__ void cpa16(uint32_t saddr, const void* g) {
    asm volatile("cp.async.ca.shared.global [%0], [%1], 16;" :: "r"(saddr), "l"(g) : "memory");
}
__device__ __forceinline__ void cpa_wait_all() {
    asm volatile("cp.async.wait_all;" ::: "memory");
}
__device__ __forceinline__ float shb1(float v) {          // butterfly xor=1
    float r;
    asm volatile("shfl.sync.bfly.b32 %0, %1, 1, 0x1f, 0xffffffff;" : "=f"(r) : "f"(v));
    return r;
}

__global__ __launch_bounds__(NT, 2)
void ip_mma_kernel(const float* __restrict__ x,
                   const float* __restrict__ gamma,
                   const float* __restrict__ beta,
                   const float* __restrict__ w1,
                   const float* __restrict__ b1,
                   const float* __restrict__ w2,
                   const float* __restrict__ b2,
                   float* __restrict__ out, int ntiles)
{
    extern __shared__ char smc[];
    const uint32_t sb = s2u(smc);
    __half* w1s = (__half*)(smc + SO_W1);
    __half* w2s = (__half*)(smc + SO_W2);
    float*  b1s = (float*)(smc + SO_B1);
    float*  b2s = (float*)(smc + SO_B2);
    float*  gs  = (float*)(smc + SO_G);
    float*  bts = (float*)(smc + SO_BT);

    const int tid  = threadIdx.x;
    const int warp = tid >> 5;
    const int lane = tid & 31;
    const int g    = lane >> 2;       // row group 0..7
    const int tc   = lane & 3;        // col pair  0..3
    const bool ev  = (tc & 1) == 0;   // even tc: keeps j=0,1 quads; odd keeps j=2,3

    // per-warp x-stage slice (32 rows x 25 f32 = 3200B)
    const uint32_t xs_warp = sb + SO_XS + warp * WBYTES;

    // ---- async stage of FIRST tile's own slice (overlaps weight staging) ----
    {
        const char* xg = (const char*)x + (long long)blockIdx.x * TROWS * DIN * 4 + warp * WBYTES;
        for (int i = lane; i < WBYTES / 16; i += 32)
            cpa16(xs_warp + i * 16, xg + i * 16);
    }

    // ---------------- one-time weight staging ----------------
    for (int i = tid; i < 476; i += NT)                       // zero w1 K-pad rows 25..31
        ((uint32_t*)(smc + SO_W1 + 25 * W_LD * 2))[i] = 0u;
    for (int i = tid; i < DIN * DP; i += NT) {                // w1 [25x128] -> half
        int k = i >> 7, n = i & 127;
        w1s[k * W_LD + n] = __float2half_rn(w1[i]);
    }
    for (int i = tid; i < DP * DP / 4; i += NT) {             // w2 [128x128] -> half
        int k = i >> 5, n4 = i & 31;
        float4 v = ((const float4*)w2)[i];
        __half2 h01 = __floats2half2_rn(v.x, v.y);
        __half2 h23 = __floats2half2_rn(v.z, v.w);
        uint2 u;
        u.x = *(uint32_t*)&h01; u.y = *(uint32_t*)&h23;
        *(uint2*)(w2s + k * W_LD + n4 * 4) = u;
    }
    if (tid < DP) { b1s[tid] = b1[tid]; b2s[tid] = b2[tid]; }
    if (tid < DIN) { gs[tid] = gamma[tid]; bts[tid] = beta[tid]; }
    __syncthreads();   // weights/biases visible CTA-wide; ONLY CTA barrier in kernel

    const int trow0 = warp * 32;
    const int lrow = ((lane >> 3) & 1) * 8 + (lane & 7);      // row within 16x16 tile
    const int lcol = ((lane >> 4) & 1) * 8;                   // col within 16x16 tile
    const uint32_t xl  = sb + SO_XN + ((trow0 + lrow) * XN_LD + lcol) * 2;
    const uint32_t w1l = sb + SO_W1 + (lrow * W_LD + lcol) * 2;
    const uint32_t w2l = sb + SO_W2 + (lrow * W_LD + lcol) * 2;

    // epilogue constants for shuffle-coalesced stores
    const int jq0 = ev ? 0 : 2, jq1 = ev ? 1 : 3;             // quads this lane stores
    const int colq = 4 * (tc >> 1);                           // pair column offset

    // ------------- persistent tile loop: NO CTA barriers, warps free-run -------------
    for (int t = blockIdx.x; t < ntiles; t += gridDim.x) {
        const long long row0 = (long long)t * TROWS;

        cpa_wait_all();   // each lane's own-slice copies for tile t done
        __syncwarp();     // all lanes of this warp done -> slice visible warp-wide

        // ---- LayerNorm: lane l -> row trow0+l (stride-25 smem: conflict-free) ----
        {
            const float* xr = (const float*)(smc + SO_XS + warp * WBYTES) + lane * DIN;
            float v[DIN];
            float s = 0.0f, s2 = 0.0f;
            #pragma unroll
            for (int i = 0; i < DIN; i++) { v[i] = xr[i]; s += v[i]; s2 += v[i] * v[i]; }
            float mu = s * (1.0f / DIN);
            float rs = rsqrtf(s2 * (1.0f / DIN) - mu * mu + 1e-5f);
            uint32_t u[16];
            #pragma unroll
            for (int i = 0; i < 12; i++)
                u[i] = packh2((v[2*i] - mu) * rs * gs[2*i] + bts[2*i],
                              (v[2*i+1] - mu) * rs * gs[2*i+1] + bts[2*i+1]);
            u[12] = packh2((v[24] - mu) * rs * gs[24] + bts[24], 0.0f);
            u[13] = 0u; u[14] = 0u; u[15] = 0u;
            uint32_t xo = sb + SO_XN + (trow0 + lane) * (XN_LD * 2);
            #pragma unroll
            for (int q = 0; q < 4; q++)
                asm volatile("st.shared.v4.b32 [%0], {%1,%2,%3,%4};"
                             :: "r"(xo + q * 16),
                                "r"(u[4*q]), "r"(u[4*q+1]), "r"(u[4*q+2]), "r"(u[4*q+3]));
        }
        __syncwarp();   // xst reads done + xn visible (both warp-private)

        // ---- fire-and-forget stage of NEXT tile's own slice ----
        {
            int tn = t + gridDim.x;
            if (tn < ntiles) {
                const char* xg = (const char*)x + (long long)tn * TROWS * DIN * 4 + warp * WBYTES;
                for (int i = lane; i < WBYTES / 16; i += 32)
                    cpa16(xs_warp + i * 16, xg + i * 16);
            }
        }

        // ================= GEMM1 + GELU -> register A2 fragments ============
        uint32_t afr[2][2][4];
        #pragma unroll
        for (int mt = 0; mt < 2; mt++)
            #pragma unroll
            for (int kk = 0; kk < 2; kk++)
                ldsm4(afr[mt][kk], xl + (16 * mt * XN_LD + 16 * kk) * 2);

        uint32_t a2[2][8][4];
        #pragma unroll
        for (int nt = 0; nt < 8; nt++) {
            uint32_t b[2][4];
            ldsm4t(b[0], w1l + (16 * nt) * 2);
            ldsm4t(b[1], w1l + (16 * W_LD + 16 * nt) * 2);
            float2 bv0 = *(const float2*)&b1s[16 * nt + 2 * tc];
            float2 bv1 = *(const float2*)&b1s[16 * nt + 8 + 2 * tc];
            #pragma unroll
            for (int mt = 0; mt < 2; mt++) {
                float c0[4] = {bv0.x, bv0.y, bv0.x, bv0.y};
                float c1[4] = {bv1.x, bv1.y, bv1.x, bv1.y};
                #pragma unroll
                for (int kk = 0; kk < 2; kk++) {
                    mma16816(c0, afr[mt][kk], b[kk][0], b[kk][1]);
                    mma16816(c1, afr[mt][kk], b[kk][2], b[kk][3]);
                }
                a2[mt][nt][0] = packh2(gelu(c0[0]), gelu(c0[1]));
                a2[mt][nt][1] = packh2(gelu(c0[2]), gelu(c0[3]));
                a2[mt][nt][2] = packh2(gelu(c1[0]), gelu(c1[1]));
                a2[mt][nt][3] = packh2(gelu(c1[2]), gelu(c1[3]));
            }
        }

        // ================= GEMM2 in four n-quarters (regs <= 128) ===========
        #pragma unroll
        for (int nq = 0; nq < 4; nq++) {
            float c2[2][4][4];
            #pragma unroll
            for (int mt = 0; mt < 2; mt++)
                #pragma unroll
                for (int j = 0; j < 4; j++) {                 // acc init = b2
                    float2 bv = *(const float2*)&b2s[32 * nq + 8 * j + 2 * tc];
                    c2[mt][j][0] = bv.x; c2[mt][j][1] = bv.y;
                    c2[mt][j][2] = bv.x; c2[mt][j][3] = bv.y;
                }
            #pragma unroll
            for (int ks = 0; ks < 8; ks++) {
                #pragma unroll
                for (int nt = 0; nt < 2; nt++) {
                    uint32_t b[4];
                    ldsm4t(b, w2l + (16 * ks * W_LD + 32 * nq + 16 * nt) * 2);
                    #pragma unroll
                    for (int mt = 0; mt < 2; mt++) {
                        mma16816(c2[mt][2 * nt],     a2[mt][ks], b[0], b[1]);
                        mma16816(c2[mt][2 * nt + 1], a2[mt][ks], b[2], b[3]);
                    }
                }
            }
            // ---- epilogue: butterfly-coalesced STG.128 streaming stores ----
            // even-tc lanes keep quads j=0,1 and receive partner halves; odd keep j=2,3.
            #pragma unroll
            for (int mt = 0; mt < 2; mt++) {
                #pragma unroll
                for (int h = 0; h < 2; h++) {
                    // send the half the partner needs (even sends j=2,3; odd sends j=0,1)
                    float sx0 = ev ? c2[mt][2][2*h]   : c2[mt][0][2*h];
                    float sy0 = ev ? c2[mt][2][2*h+1] : c2[mt][0][2*h+1];
                    float sx1 = ev ? c2[mt][3][2*h]   : c2[mt][1][2*h];
                    float sy1 = ev ? c2[mt][3][2*h+1] : c2[mt][1][2*h+1];
                    float rx0 = shb1(sx0), ry0 = shb1(sy0);
                    float rx1 = shb1(sx1), ry1 = shb1(sy1);
                    float4 q0 = ev
                        ? make_float4(c2[mt][0][2*h], c2[mt][0][2*h+1], rx0, ry0)
                        : make_float4(rx0, ry0, c2[mt][2][2*h], c2[mt][2][2*h+1]);
                    float4 q1 = ev
                        ? make_float4(c2[mt][1][2*h], c2[mt][1][2*h+1], rx1, ry1)
                        : make_float4(rx1, ry1, c2[mt][3][2*h], c2[mt][3][2*h+1]);
                    long long r = row0 + trow0 + 16 * mt + g + 8 * h;
                    float* orow = out + r * DP + 32 * nq + colq;
                    __stcs((float4*)(orow + 8 * jq0), q0);
                    __stcs((float4*)(orow + 8 * jq1), q1);
                }
            }
        }
    }
}

extern "C" void kernel_launch(void* const* d_in, const int* in_sizes, int n_in,
                              void* d_out, int out_size)
{
    const float* x     = (const float*)d_in[0];
    const float* gamma = (const float*)d_in[1];
    const float* beta  = (const float*)d_in[2];
    const float* w1    = (const float*)d_in[3];
    const float* b1    = (const float*)d_in[4];
    const float* w2    = (const float*)d_in[5];
    const float* b2    = (const float*)d_in[6];
    float* out = (float*)d_out;

    static int n_sm = 0;   // one-time query + attribute set (not a work guard)
    if (n_sm == 0) {
        cudaDeviceProp prop;
        cudaGetDeviceProperties(&prop, 0);
        n_sm = prop.multiProcessorCount;
        cudaFuncSetAttribute(ip_mma_kernel,
                             cudaFuncAttributeMaxDynamicSharedMemorySize,
                             SMEM_BYTES);
    }

    const int rows = in_sizes[0] / DIN;   // 524288
    const int ntiles = rows / TROWS;      // 2048
    const int grid = n_sm * 2;            // persistent: 2 CTAs/SM
    ip_mma_kernel<<<grid, NT, SMEM_BYTES>>>(x, gamma, beta, w1, b1, w2, b2, out, ntiles);
}

// round 16
// speedup vs baseline: 1.0548x; 1.0548x over previous
#include <cuda_runtime.h>
#include <cuda_fp16.h>
#include <cstdint>

#define DIN   25
#define DP    128
#define NT    256        // 8 warps; warp w owns rows 32w..32w+31 of a 256-row tile
#define TROWS 256        // rows per CTA tile
#define W_LD  136        // halves per weight row (272B, conflict-free under ldmatrix)
#define XN_LD 40         // halves per xn row (80B)
#define WBYTES 3200      // per-warp x slice: 32 rows x 25 f32

// shared byte offsets (16B aligned)
#define SO_W1  0         // 32x136 half   = 8704
#define SO_W2  8704      // 128x136 half  = 34816
#define SO_XN  43520     // 256x40 half   = 20480
#define SO_XS  64000     // 256x25 f32    = 25600
#define SO_B1  89600     // 512
#define SO_B2  90112     // 512
#define SO_G   90624     // 128
#define SO_BT  90752     // 128
#define SMEM_BYTES 90880 // x2 CTAs fits 228KB/SM

__device__ __forceinline__ uint32_t s2u(const void* p) {
    uint32_t a;
    asm("{ .reg .u64 t; cvta.to.shared.u64 t, %1; cvt.u32.u64 %0, t; }" : "=r"(a) : "l"(p));
    return a;
}
__device__ __forceinline__ void ldsm4(uint32_t* r, uint32_t addr) {
    asm volatile("ldmatrix.sync.aligned.m8n8.x4.shared.b16 {%0,%1,%2,%3}, [%4];"
                 : "=r"(r[0]), "=r"(r[1]), "=r"(r[2]), "=r"(r[3]) : "r"(addr));
}
__device__ __forceinline__ void ldsm4t(uint32_t* r, uint32_t addr) {
    asm volatile("ldmatrix.sync.aligned.m8n8.x4.trans.shared.b16 {%0,%1,%2,%3}, [%4];"
                 : "=r"(r[0]), "=r"(r[1]), "=r"(r[2]), "=r"(r[3]) : "r"(addr));
}
__device__ __forceinline__ void mma16816(float* c, const uint32_t* a, uint32_t b0, uint32_t b1) {
    asm volatile("mma.sync.aligned.m16n8k16.row.col.f32.f16.f16.f32 "
                 "{%0,%1,%2,%3}, {%4,%5,%6,%7}, {%8,%9}, {%0,%1,%2,%3};"
                 : "+f"(c[0]), "+f"(c[1]), "+f"(c[2]), "+f"(c[3])
                 : "r"(a[0]), "r"(a[1]), "r"(a[2]), "r"(a[3]), "r"(b0), "r"(b1));
}
__device__ __forceinline__ uint32_t packh2(float lo, float hi) {
    __half2 h = __floats2half2_rn(lo, hi);
    return *(uint32_t*)&h;
}
// Pairwise tanh-form GELU: u in f32 (accurate), tanh + finish in half2.
// One MUFU (tanh.approx.f16x2) per TWO values.
__device__ __forceinline__ uint32_t gelu2(float v0, float v1) {
    float u0 = 0.7978845608028654f * fmaf(0.044715f * v0, v0 * v0, v0);
    float u1 = 0.7978845608028654f * fmaf(0.044715f * v1, v1 * v1, v1);
    uint32_t uh = packh2(u0, u1);
    uint32_t vh = packh2(v0, v1);
    uint32_t th;
    asm volatile("tanh.approx.f16x2 %0, %1;" : "=r"(th) : "r"(uh));
    __half2 half_ = __float2half2_rn(0.5f);
    __half2 t2 = *(__half2*)&th;
    __half2 g = __hmul2(*(__half2*)&vh, __hfma2(t2, half_, half_));
    return *(uint32_t*)&g;
}
__device__ __forceinline__ void cpa16(uint32_t saddr, const void* g) {
    asm volatile("cp.async.ca.shared.global [%0], [%1], 16;" :: "r"(saddr), "l"(g) : "memory");
}
__device__ __forceinline__ void cpa_wait_all() {
    asm volatile("cp.async.wait_all;" ::: "memory");
}

__global__ __launch_bounds__(NT, 2)
void ip_mma_kernel(const float* __restrict__ x,
                   const float* __restrict__ gamma,
                   const float* __restrict__ beta,
                   const float* __restrict__ w1,
                   const float* __restrict__ b1,
                   const float* __restrict__ w2,
                   const float* __restrict__ b2,
                   float* __restrict__ out, int ntiles)
{
    extern __shared__ char smc[];
    const uint32_t sb = s2u(smc);
    __half* w1s = (__half*)(smc + SO_W1);
    __half* w2s = (__half*)(smc + SO_W2);
    float*  b1s = (float*)(smc + SO_B1);
    float*  b2s = (float*)(smc + SO_B2);
    float*  gs  = (float*)(smc + SO_G);
    float*  bts = (float*)(smc + SO_BT);

    const int tid  = threadIdx.x;
    const int warp = tid >> 5;
    const int lane = tid & 31;
    const int g    = lane >> 2;       // row group 0..7
    const int tc   = lane & 3;        // col pair  0..3

    // per-warp x-stage slice (32 rows x 25 f32 = 3200B)
    const uint32_t xs_warp = sb + SO_XS + warp * WBYTES;

    // ---- async stage of FIRST tile's own slice (overlaps weight staging) ----
    {
        const char* xg = (const char*)x + (long long)blockIdx.x * TROWS * DIN * 4 + warp * WBYTES;
        for (int i = lane; i < WBYTES / 16; i += 32)
            cpa16(xs_warp + i * 16, xg + i * 16);
    }

    // ---------------- one-time weight staging ----------------
    for (int i = tid; i < 476; i += NT)                       // zero w1 K-pad rows 25..31
        ((uint32_t*)(smc + SO_W1 + 25 * W_LD * 2))[i] = 0u;
    for (int i = tid; i < DIN * DP; i += NT) {                // w1 [25x128] -> half
        int k = i >> 7, n = i & 127;
        w1s[k * W_LD + n] = __float2half_rn(w1[i]);
    }
    for (int i = tid; i < DP * DP / 4; i += NT) {             // w2 [128x128] -> half
        int k = i >> 5, n4 = i & 31;
        float4 v = ((const float4*)w2)[i];
        __half2 h01 = __floats2half2_rn(v.x, v.y);
        __half2 h23 = __floats2half2_rn(v.z, v.w);
        uint2 u;
        u.x = *(uint32_t*)&h01; u.y = *(uint32_t*)&h23;
        *(uint2*)(w2s + k * W_LD + n4 * 4) = u;
    }
    if (tid < DP) { b1s[tid] = b1[tid]; b2s[tid] = b2[tid]; }
    if (tid < DIN) { gs[tid] = gamma[tid]; bts[tid] = beta[tid]; }
    __syncthreads();   // weights/biases visible CTA-wide; ONLY CTA barrier in kernel

    const int trow0 = warp * 32;
    const int lrow = ((lane >> 3) & 1) * 8 + (lane & 7);      // row within 16x16 tile
    const int lcol = ((lane >> 4) & 1) * 8;                   // col within 16x16 tile
    const uint32_t xl  = sb + SO_XN + ((trow0 + lrow) * XN_LD + lcol) * 2;
    const uint32_t w1l = sb + SO_W1 + (lrow * W_LD + lcol) * 2;
    const uint32_t w2l = sb + SO_W2 + (lrow * W_LD + lcol) * 2;

    // ------------- persistent tile loop: NO CTA barriers, warps free-run -------------
    for (int t = blockIdx.x; t < ntiles; t += gridDim.x) {
        const long long row0 = (long long)t * TROWS;

        cpa_wait_all();   // each lane's own-slice copies for tile t done
        __syncwarp();     // all lanes of this warp done -> slice visible warp-wide

        // ---- LayerNorm: lane l -> row trow0+l (stride-25 smem: conflict-free) ----
        {
            const float* xr = (const float*)(smc + SO_XS + warp * WBYTES) + lane * DIN;
            float v[DIN];
            float s = 0.0f, s2 = 0.0f;
            #pragma unroll
            for (int i = 0; i < DIN; i++) { v[i] = xr[i]; s += v[i]; s2 += v[i] * v[i]; }
            float mu = s * (1.0f / DIN);
            float rs = rsqrtf(s2 * (1.0f / DIN) - mu * mu + 1e-5f);
            uint32_t u[16];
            #pragma unroll
            for (int i = 0; i < 12; i++)
                u[i] = packh2((v[2*i] - mu) * rs * gs[2*i] + bts[2*i],
                              (v[2*i+1] - mu) * rs * gs[2*i+1] + bts[2*i+1]);
            u[12] = packh2((v[24] - mu) * rs * gs[24] + bts[24], 0.0f);
            u[13] = 0u; u[14] = 0u; u[15] = 0u;
            uint32_t xo = sb + SO_XN + (trow0 + lane) * (XN_LD * 2);
            #pragma unroll
            for (int q = 0; q < 4; q++)
                asm volatile("st.shared.v4.b32 [%0], {%1,%2,%3,%4};"
                             :: "r"(xo + q * 16),
                                "r"(u[4*q]), "r"(u[4*q+1]), "r"(u[4*q+2]), "r"(u[4*q+3]));
        }
        __syncwarp();   // xst reads done + xn visible (both warp-private)

        // ---- fire-and-forget stage of NEXT tile's own slice ----
        {
            int tn = t + gridDim.x;
            if (tn < ntiles) {
                const char* xg = (const char*)x + (long long)tn * TROWS * DIN * 4 + warp * WBYTES;
                for (int i = lane; i < WBYTES / 16; i += 32)
                    cpa16(xs_warp + i * 16, xg + i * 16);
            }
        }

        // ================= GEMM1 + GELU -> register A2 fragments ============
        uint32_t afr[2][2][4];
        #pragma unroll
        for (int mt = 0; mt < 2; mt++)
            #pragma unroll
            for (int kk = 0; kk < 2; kk++)
                ldsm4(afr[mt][kk], xl + (16 * mt * XN_LD + 16 * kk) * 2);

        uint32_t a2[2][8][4];
        #pragma unroll
        for (int nt = 0; nt < 8; nt++) {
            uint32_t b[2][4];
            ldsm4t(b[0], w1l + (16 * nt) * 2);
            ldsm4t(b[1], w1l + (16 * W_LD + 16 * nt) * 2);
            float2 bv0 = *(const float2*)&b1s[16 * nt + 2 * tc];
            float2 bv1 = *(const float2*)&b1s[16 * nt + 8 + 2 * tc];
            #pragma unroll
            for (int mt = 0; mt < 2; mt++) {
                float c0[4] = {bv0.x, bv0.y, bv0.x, bv0.y};
                float c1[4] = {bv1.x, bv1.y, bv1.x, bv1.y};
                #pragma unroll
                for (int kk = 0; kk < 2; kk++) {
                    mma16816(c0, afr[mt][kk], b[kk][0], b[kk][1]);
                    mma16816(c1, afr[mt][kk], b[kk][2], b[kk][3]);
                }
                a2[mt][nt][0] = gelu2(c0[0], c0[1]);
                a2[mt][nt][1] = gelu2(c0[2], c0[3]);
                a2[mt][nt][2] = gelu2(c1[0], c1[1]);
                a2[mt][nt][3] = gelu2(c1[2], c1[3]);
            }
        }

        // ================= GEMM2 in four n-quarters (regs <= 128) ===========
        #pragma unroll
        for (int nq = 0; nq < 4; nq++) {
            float c2[2][4][4];
            #pragma unroll
            for (int mt = 0; mt < 2; mt++)
                #pragma unroll
                for (int j = 0; j < 4; j++) {                 // acc init = b2
                    float2 bv = *(const float2*)&b2s[32 * nq + 8 * j + 2 * tc];
                    c2[mt][j][0] = bv.x; c2[mt][j][1] = bv.y;
                    c2[mt][j][2] = bv.x; c2[mt][j][3] = bv.y;
                }
            #pragma unroll
            for (int ks = 0; ks < 8; ks++) {
                #pragma unroll
                for (int nt = 0; nt < 2; nt++) {
                    uint32_t b[4];
                    ldsm4t(b, w2l + (16 * ks * W_LD + 32 * nq + 16 * nt) * 2);
                    #pragma unroll
                    for (int mt = 0; mt < 2; mt++) {
                        mma16816(c2[mt][2 * nt],     a2[mt][ks], b[0], b[1]);
                        mma16816(c2[mt][2 * nt + 1], a2[mt][ks], b[2], b[3]);
                    }
                }
            }
            // epilogue: direct streaming float2 stores (output never re-read)
            #pragma unroll
            for (int mt = 0; mt < 2; mt++) {
                long long r = row0 + trow0 + 16 * mt + g;
                #pragma unroll
                for (int j = 0; j < 4; j++) {
                    int col = 32 * nq + 8 * j + 2 * tc;
                    __stcs((float2*)(out + r * DP + col),
                           make_float2(c2[mt][j][0], c2[mt][j][1]));
                    __stcs((float2*)(out + (r + 8) * DP + col),
                           make_float2(c2[mt][j][2], c2[mt][j][3]));
                }
            }
        }
    }
}

extern "C" void kernel_launch(void* const* d_in, const int* in_sizes, int n_in,
                              void* d_out, int out_size)
{
    const float* x     = (const float*)d_in[0];
    const float* gamma = (const float*)d_in[1];
    const float* beta  = (const float*)d_in[2];
    const float* w1    = (const float*)d_in[3];
    const float* b1    = (const float*)d_in[4];
    const float* w2    = (const float*)d_in[5];
    const float* b2    = (const float*)d_in[6];
    float* out = (float*)d_out;

    static int n_sm = 0;   // one-time query + attribute set (not a work guard)
    if (n_sm == 0) {
        cudaDeviceProp prop;
        cudaGetDeviceProperties(&prop, 0);
        n_sm = prop.multiProcessorCount;
        cudaFuncSetAttribute(ip_mma_kernel,
                             cudaFuncAttributeMaxDynamicSharedMemorySize,
                             SMEM_BYTES);
    }

    const int rows = in_sizes[0] / DIN;   // 524288
    const int ntiles = rows / TROWS;      // 2048
    const int grid = n_sm * 2;            // persistent: 2 CTAs/SM
    ip_mma_kernel<<<grid, NT, SMEM_BYTES>>>(x, gamma, beta, w1, b1, w2, b2, out, ntiles);
}

// round 17
// speedup vs baseline: 1.0735x; 1.0177x over previous
#include <cuda_runtime.h>
#include <cuda_fp16.h>
#include <cstdint>

#define DIN   25
#define DP    128
#define NT    256        // 8 warps; each warp = independent worker on 32-row units
#define W_LD  136        // halves per weight row (272B, conflict-free under ldmatrix)
#define XN_LD 40         // halves per xn row (80B)
#define WBYTES 3200      // per-unit x slice: 32 rows x 25 f32

// shared byte offsets (16B aligned)
#define SO_W1  0         // 32x136 half   = 8704
#define SO_W2  8704      // 128x136 half  = 34816
#define SO_XN  43520     // 256x40 half   = 20480
#define SO_XS  64000     // 256x25 f32    = 25600 (8 per-warp slices)
#define SO_B1  89600     // 512
#define SO_B2  90112     // 512
#define SO_G   90624     // 128
#define SO_BT  90752     // 128
#define SMEM_BYTES 90880 // x2 CTAs fits 228KB/SM

__device__ unsigned int g_tile_ctr;   // reset to 0 by cudaMemsetAsync each launch

__device__ __forceinline__ uint32_t s2u(const void* p) {
    uint32_t a;
    asm("{ .reg .u64 t; cvta.to.shared.u64 t, %1; cvt.u32.u64 %0, t; }" : "=r"(a) : "l"(p));
    return a;
}
__device__ __forceinline__ void ldsm4(uint32_t* r, uint32_t addr) {
    asm volatile("ldmatrix.sync.aligned.m8n8.x4.shared.b16 {%0,%1,%2,%3}, [%4];"
                 : "=r"(r[0]), "=r"(r[1]), "=r"(r[2]), "=r"(r[3]) : "r"(addr));
}
__device__ __forceinline__ void ldsm4t(uint32_t* r, uint32_t addr) {
    asm volatile("ldmatrix.sync.aligned.m8n8.x4.trans.shared.b16 {%0,%1,%2,%3}, [%4];"
                 : "=r"(r[0]), "=r"(r[1]), "=r"(r[2]), "=r"(r[3]) : "r"(addr));
}
__device__ __forceinline__ void mma16816(float* c, const uint32_t* a, uint32_t b0, uint32_t b1) {
    asm volatile("mma.sync.aligned.m16n8k16.row.col.f32.f16.f16.f32 "
                 "{%0,%1,%2,%3}, {%4,%5,%6,%7}, {%8,%9}, {%0,%1,%2,%3};"
                 : "+f"(c[0]), "+f"(c[1]), "+f"(c[2]), "+f"(c[3])
                 : "r"(a[0]), "r"(a[1]), "r"(a[2]), "r"(a[3]), "r"(b0), "r"(b1));
}
__device__ __forceinline__ uint32_t packh2(float lo, float hi) {
    __half2 h = __floats2half2_rn(lo, hi);
    return *(uint32_t*)&h;
}
// Pairwise tanh-form GELU: u = v*fma(v^2,c1,c0) in f32, tanh + finish in half2.
__device__ __forceinline__ uint32_t gelu2(float v0, float v1) {
    const float c0 = 0.7978845608028654f, c1 = 0.03567740813636141f;
    float u0 = v0 * fmaf(v0 * v0, c1, c0);
    float u1 = v1 * fmaf(v1 * v1, c1, c0);
    uint32_t uh = packh2(u0, u1);
    uint32_t vh = packh2(v0, v1);
    uint32_t th;
    asm volatile("tanh.approx.f16x2 %0, %1;" : "=r"(th) : "r"(uh));
    __half2 half_ = __float2half2_rn(0.5f);
    __half2 t2 = *(__half2*)&th;
    __half2 g = __hmul2(*(__half2*)&vh, __hfma2(t2, half_, half_));
    return *(uint32_t*)&g;
}
__device__ __forceinline__ void cpa16(uint32_t saddr, const void* g) {
    asm volatile("cp.async.ca.shared.global [%0], [%1], 16;" :: "r"(saddr), "l"(g) : "memory");
}
__device__ __forceinline__ void cpa_wait_all() {
    asm volatile("cp.async.wait_all;" ::: "memory");
}

__global__ __launch_bounds__(NT, 2)
void ip_mma_kernel(const float* __restrict__ x,
                   const float* __restrict__ gamma,
                   const float* __restrict__ beta,
                   const float* __restrict__ w1,
                   const float* __restrict__ b1,
                   const float* __restrict__ w2,
                   const float* __restrict__ b2,
                   float* __restrict__ out, int nunits)
{
    extern __shared__ char smc[];
    const uint32_t sb = s2u(smc);
    __half* w1s = (__half*)(smc + SO_W1);
    __half* w2s = (__half*)(smc + SO_W2);
    float*  b1s = (float*)(smc + SO_B1);
    float*  b2s = (float*)(smc + SO_B2);
    float*  gs  = (float*)(smc + SO_G);
    float*  bts = (float*)(smc + SO_BT);

    const int tid  = threadIdx.x;
    const int warp = tid >> 5;
    const int lane = tid & 31;
    const int g    = lane >> 2;       // row group 0..7
    const int tc   = lane & 3;        // col pair  0..3

    // per-warp x-stage slice (32 rows x 25 f32 = 3200B)
    const uint32_t xs_warp = sb + SO_XS + warp * WBYTES;

    // ---- steal FIRST unit and stage it (overlaps weight staging) ----
    unsigned t32;
    if (lane == 0) t32 = atomicAdd(&g_tile_ctr, 1u);
    t32 = __shfl_sync(0xffffffffu, t32, 0);
    if (t32 < (unsigned)nunits) {
        const char* xg = (const char*)x + (long long)t32 * WBYTES;
        for (int i = lane; i < WBYTES / 16; i += 32)
            cpa16(xs_warp + i * 16, xg + i * 16);
    }

    // ---------------- one-time weight staging ----------------
    for (int i = tid; i < 476; i += NT)                       // zero w1 K-pad rows 25..31
        ((uint32_t*)(smc + SO_W1 + 25 * W_LD * 2))[i] = 0u;
    for (int i = tid; i < DIN * DP; i += NT) {                // w1 [25x128] -> half
        int k = i >> 7, n = i & 127;
        w1s[k * W_LD + n] = __float2half_rn(w1[i]);
    }
    for (int i = tid; i < DP * DP / 4; i += NT) {             // w2 [128x128] -> half
        int k = i >> 5, n4 = i & 31;
        float4 v = ((const float4*)w2)[i];
        __half2 h01 = __floats2half2_rn(v.x, v.y);
        __half2 h23 = __floats2half2_rn(v.z, v.w);
        uint2 u;
        u.x = *(uint32_t*)&h01; u.y = *(uint32_t*)&h23;
        *(uint2*)(w2s + k * W_LD + n4 * 4) = u;
    }
    if (tid < DP) { b1s[tid] = b1[tid]; b2s[tid] = b2[tid]; }
    if (tid < DIN) { gs[tid] = gamma[tid]; bts[tid] = beta[tid]; }
    __syncthreads();   // weights/biases visible CTA-wide; ONLY CTA barrier in kernel

    const int trow0 = warp * 32;
    const int lrow = ((lane >> 3) & 1) * 8 + (lane & 7);      // row within 16x16 tile
    const int lcol = ((lane >> 4) & 1) * 8;                   // col within 16x16 tile
    const uint32_t xl  = sb + SO_XN + ((trow0 + lrow) * XN_LD + lcol) * 2;
    const uint32_t w1l = sb + SO_W1 + (lrow * W_LD + lcol) * 2;
    const uint32_t w2l = sb + SO_W2 + (lrow * W_LD + lcol) * 2;

    // ------------- per-warp work-stealing loop: warps fully independent -------------
    while (t32 < (unsigned)nunits) {
        cpa_wait_all();   // own-slice copies for unit t32 done
        __syncwarp();     // slice visible warp-wide

        // ---- LayerNorm: lane l -> unit row l (stride-25 smem: conflict-free) ----
        {
            const float* xr = (const float*)(smc + SO_XS + warp * WBYTES) + lane * DIN;
            float v[DIN];
            float s = 0.0f, s2 = 0.0f;
            #pragma unroll
            for (int i = 0; i < DIN; i++) { v[i] = xr[i]; s += v[i]; s2 += v[i] * v[i]; }
            float mu = s * (1.0f / DIN);
            float rs = rsqrtf(s2 * (1.0f / DIN) - mu * mu + 1e-5f);
            uint32_t u[16];
            #pragma unroll
            for (int i = 0; i < 12; i++)
                u[i] = packh2((v[2*i] - mu) * rs * gs[2*i] + bts[2*i],
                              (v[2*i+1] - mu) * rs * gs[2*i+1] + bts[2*i+1]);
            u[12] = packh2((v[24] - mu) * rs * gs[24] + bts[24], 0.0f);
            u[13] = 0u; u[14] = 0u; u[15] = 0u;
            uint32_t xo = sb + SO_XN + (trow0 + lane) * (XN_LD * 2);
            #pragma unroll
            for (int q = 0; q < 4; q++)
                asm volatile("st.shared.v4.b32 [%0], {%1,%2,%3,%4};"
                             :: "r"(xo + q * 16),
                                "r"(u[4*q]), "r"(u[4*q+1]), "r"(u[4*q+2]), "r"(u[4*q+3]));
        }
        __syncwarp();   // xst reads done + xn visible (both warp-private)

        // ---- steal NEXT unit, fire-and-forget its stage (lands under GEMMs) ----
        unsigned tn;
        if (lane == 0) tn = atomicAdd(&g_tile_ctr, 1u);
        tn = __shfl_sync(0xffffffffu, tn, 0);
        if (tn < (unsigned)nunits) {
            const char* xg = (const char*)x + (long long)tn * WBYTES;
            for (int i = lane; i < WBYTES / 16; i += 32)
                cpa16(xs_warp + i * 16, xg + i * 16);
        }

        // ================= GEMM1 + GELU -> register A2 fragments ============
        uint32_t afr[2][2][4];
        #pragma unroll
        for (int mt = 0; mt < 2; mt++)
            #pragma unroll
            for (int kk = 0; kk < 2; kk++)
                ldsm4(afr[mt][kk], xl + (16 * mt * XN_LD + 16 * kk) * 2);

        uint32_t a2[2][8][4];
        #pragma unroll
        for (int nt = 0; nt < 8; nt++) {
            uint32_t b[2][4];
            ldsm4t(b[0], w1l + (16 * nt) * 2);
            ldsm4t(b[1], w1l + (16 * W_LD + 16 * nt) * 2);
            float2 bv0 = *(const float2*)&b1s[16 * nt + 2 * tc];
            float2 bv1 = *(const float2*)&b1s[16 * nt + 8 + 2 * tc];
            #pragma unroll
            for (int mt = 0; mt < 2; mt++) {
                float c0[4] = {bv0.x, bv0.y, bv0.x, bv0.y};
                float c1[4] = {bv1.x, bv1.y, bv1.x, bv1.y};
                #pragma unroll
                for (int kk = 0; kk < 2; kk++) {
                    mma16816(c0, afr[mt][kk], b[kk][0], b[kk][1]);
                    mma16816(c1, afr[mt][kk], b[kk][2], b[kk][3]);
                }
                a2[mt][nt][0] = gelu2(c0[0], c0[1]);
                a2[mt][nt][1] = gelu2(c0[2], c0[3]);
                a2[mt][nt][2] = gelu2(c1[0], c1[1]);
                a2[mt][nt][3] = gelu2(c1[2], c1[3]);
            }
        }

        // ================= GEMM2 in four n-quarters (regs <= 128) ===========
        #pragma unroll
        for (int nq = 0; nq < 4; nq++) {
            float c2[2][4][4];
            #pragma unroll
            for (int mt = 0; mt < 2; mt++)
                #pragma unroll
                for (int j = 0; j < 4; j++) {                 // acc init = b2
                    float2 bv = *(const float2*)&b2s[32 * nq + 8 * j + 2 * tc];
                    c2[mt][j][0] = bv.x; c2[mt][j][1] = bv.y;
                    c2[mt][j][2] = bv.x; c2[mt][j][3] = bv.y;
                }
            #pragma unroll
            for (int ks = 0; ks < 8; ks++) {
                #pragma unroll
                for (int nt = 0; nt < 2; nt++) {
                    uint32_t b[4];
                    ldsm4t(b, w2l + (16 * ks * W_LD + 32 * nq + 16 * nt) * 2);
                    #pragma unroll
                    for (int mt = 0; mt < 2; mt++) {
                        mma16816(c2[mt][2 * nt],     a2[mt][ks], b[0], b[1]);
                        mma16816(c2[mt][2 * nt + 1], a2[mt][ks], b[2], b[3]);
                    }
                }
            }
            // epilogue: direct streaming float2 stores (output never re-read)
            #pragma unroll
            for (int mt = 0; mt < 2; mt++) {
                long long r = (long long)t32 * 32 + 16 * mt + g;
                #pragma unroll
                for (int j = 0; j < 4; j++) {
                    int col = 32 * nq + 8 * j + 2 * tc;
                    __stcs((float2*)(out + r * DP + col),
                           make_float2(c2[mt][j][0], c2[mt][j][1]));
                    __stcs((float2*)(out + (r + 8) * DP + col),
                           make_float2(c2[mt][j][2], c2[mt][j][3]));
                }
            }
        }

        t32 = tn;
    }
}

extern "C" void kernel_launch(void* const* d_in, const int* in_sizes, int n_in,
                              void* d_out, int out_size)
{
    const float* x     = (const float*)d_in[0];
    const float* gamma = (const float*)d_in[1];
    const float* beta  = (const float*)d_in[2];
    const float* w1    = (const float*)d_in[3];
    const float* b1    = (const float*)d_in[4];
    const float* w2    = (const float*)d_in[5];
    const float* b2    = (const float*)d_in[6];
    float* out = (float*)d_out;

    static int n_sm = 0;            // one-time query + attribute set (not a work guard)
    static void* ctr_addr = nullptr;
    if (n_sm == 0) {
        cudaDeviceProp prop;
        cudaGetDeviceProperties(&prop, 0);
        n_sm = prop.multiProcessorCount;
        cudaFuncSetAttribute(ip_mma_kernel,
                             cudaFuncAttributeMaxDynamicSharedMemorySize,
                             SMEM_BYTES);
        cudaGetSymbolAddress(&ctr_addr, g_tile_ctr);
    }

    const int rows = in_sizes[0] / DIN;   // 524288
    const int nunits = rows / 32;         // 16384 warp-units
    const int grid = n_sm * 2;            // persistent: 2 CTAs/SM

    cudaMemsetAsync(ctr_addr, 0, sizeof(unsigned int));   // reset work counter (capturable)
    ip_mma_kernel<<<grid, NT, SMEM_BYTES>>>(x, gamma, beta, w1, b1, w2, b2, out, nunits);
}